// round 9
// baseline (speedup 1.0000x reference)
#include <cuda_runtime.h>

// CosinLoss fully fused, single kernel: loss = mean_i(1 - cos(pc_i, aug_i)).
// N=16384 rows, D=1024 fp32 (128 MiB streamed).
// 4 rows per 256-thread CTA (64 thr/row, 4 float4/tensor/thread -> MLP_p1=8), grid 4096.
// Epilogue: fixed-point u64 atomicAdd into ONE OF 64 SHARDS (each on its own 128B
// line -> 64-way lower L2 atomic contention than R8's single address), plus a u32
// wrapping arrival counter. The counter add data-depends on the shard-add return,
// so count==GRID-1 implies all shard adds are globally performed. Last CTA sums the
// 64 shards with integer adds (bit-deterministic), writes the mean, re-zeros shards.

#define CL_N   16384
#define CL_D   1024
#define CL_EPS 1e-12f
#define GRID1  4096
#define NSHARD 64
#define SHARD_STRIDE 16            // u64s; 16*8 = 128B line per shard
#define FP_SCALE  4294967296.0    // 2^32
#define BIAS      8.0             // partial in (-8,16); biased -> (0,24); 4096*24*2^32 < 2^49

__device__ unsigned long long g_shard[NSHARD * SHARD_STRIDE];
__device__ unsigned int g_count = 0;

__global__ __launch_bounds__(256)
void cos_loss_fused(const float* __restrict__ pc, const float* __restrict__ aug,
                    float* __restrict__ out) {
    const int t    = threadIdx.x;
    const int wid  = t >> 5;        // 0..7; warps 2r,2r+1 own row r
    const int lane = t & 31;
    const int rsub = t >> 6;        // 0..3: row within CTA
    const int ct   = t & 63;        // thread index within row (64 thr/row)
    const size_t row = (size_t)blockIdx.x * 4 + rsub;

    const float4* __restrict__ p4 = reinterpret_cast<const float4*>(pc  + row * CL_D);
    const float4* __restrict__ a4 = reinterpret_cast<const float4*>(aug + row * CL_D);

    // 8 outstanding LDG.128 per thread, streaming hint.
    float4 p0 = __ldcs(&p4[ct      ]);
    float4 p1 = __ldcs(&p4[ct +  64]);
    float4 p2 = __ldcs(&p4[ct + 128]);
    float4 p3 = __ldcs(&p4[ct + 192]);
    float4 a0 = __ldcs(&a4[ct      ]);
    float4 a1 = __ldcs(&a4[ct +  64]);
    float4 a2 = __ldcs(&a4[ct + 128]);
    float4 a3 = __ldcs(&a4[ct + 192]);

    float dot = p0.x*a0.x + p0.y*a0.y + p0.z*a0.z + p0.w*a0.w
              + p1.x*a1.x + p1.y*a1.y + p1.z*a1.z + p1.w*a1.w
              + p2.x*a2.x + p2.y*a2.y + p2.z*a2.z + p2.w*a2.w
              + p3.x*a3.x + p3.y*a3.y + p3.z*a3.z + p3.w*a3.w;
    float npp = p0.x*p0.x + p0.y*p0.y + p0.z*p0.z + p0.w*p0.w
              + p1.x*p1.x + p1.y*p1.y + p1.z*p1.z + p1.w*p1.w
              + p2.x*p2.x + p2.y*p2.y + p2.z*p2.z + p2.w*p2.w
              + p3.x*p3.x + p3.y*p3.y + p3.z*p3.z + p3.w*p3.w;
    float naa = a0.x*a0.x + a0.y*a0.y + a0.z*a0.z + a0.w*a0.w
              + a1.x*a1.x + a1.y*a1.y + a1.z*a1.z + a1.w*a1.w
              + a2.x*a2.x + a2.y*a2.y + a2.z*a2.z + a2.w*a2.w
              + a3.x*a3.x + a3.y*a3.y + a3.z*a3.z + a3.w*a3.w;

    #pragma unroll
    for (int off = 16; off > 0; off >>= 1) {
        dot += __shfl_down_sync(0xFFFFFFFFu, dot, off);
        npp += __shfl_down_sync(0xFFFFFFFFu, npp, off);
        naa += __shfl_down_sync(0xFFFFFFFFu, naa, off);
    }

    __shared__ float s_dot[8], s_npp[8], s_naa[8];
    if (lane == 0) {
        s_dot[wid] = dot;
        s_npp[wid] = npp;
        s_naa[wid] = naa;
    }
    __syncthreads();

    // Warp 0, lanes 0..7: slot pairs (2r, 2r+1) belong to row r.
    if (wid == 0 && lane < 8) {
        dot = s_dot[lane];
        npp = s_npp[lane];
        naa = s_naa[lane];
        dot += __shfl_xor_sync(0x000000FFu, dot, 1);
        npp += __shfl_xor_sync(0x000000FFu, npp, 1);
        naa += __shfl_xor_sync(0x000000FFu, naa, 1);

        float loss = 0.0f;
        if ((lane & 1) == 0) {
            float np_ = fmaxf(sqrtf(npp), CL_EPS);
            float na_ = fmaxf(sqrtf(naa), CL_EPS);
            loss = 1.0f - dot / (np_ * na_);
        }
        loss += __shfl_down_sync(0x000000FFu, loss, 4);
        loss += __shfl_down_sync(0x000000FFu, loss, 2);

        if (lane == 0) {
            // Fixed-point encode (always non-negative thanks to bias).
            unsigned long long fp =
                (unsigned long long)((double)loss * FP_SCALE + BIAS * FP_SCALE + 0.5);
            const int shard = (blockIdx.x & (NSHARD - 1)) * SHARD_STRIDE;
            unsigned long long old = atomicAdd(&g_shard[shard], fp);

            // Data-depend the counter add on the shard add's completion:
            // fp sums < 2^49, so old>>63 == 0 always, but the compiler can't prove it.
            unsigned int dep = (unsigned int)(old >> 63);
            unsigned int prev = atomicInc(&g_count, GRID1 - 1 + dep); // wraps at GRID1-1

            if (prev == GRID1 - 1) {
                // All shard adds globally performed (each counter inc was issued
                // only after its CTA's shard add completed at L2).
                unsigned long long total = 0ULL;
                #pragma unroll
                for (int i = 0; i < NSHARD; i++) {
                    total += __ldcg(&g_shard[i * SHARD_STRIDE]);
                    g_shard[i * SHARD_STRIDE] = 0ULL;   // reset for next graph replay
                }
                double sum = (double)total * (1.0 / FP_SCALE) - BIAS * (double)GRID1;
                out[0] = (float)(sum * (1.0 / (double)CL_N));
            }
        }
    }
}

extern "C" void kernel_launch(void* const* d_in, const int* in_sizes, int n_in,
                              void* d_out, int out_size) {
    const float* pc  = (const float*)d_in[0];
    const float* aug = (const float*)d_in[1];
    float* out = (float*)d_out;

    cos_loss_fused<<<GRID1, 256>>>(pc, aug, out);
}

// round 10
// speedup vs baseline: 1.1041x; 1.1041x over previous
#include <cuda_runtime.h>

// CosinLoss fully fused, single kernel: loss = mean_i(1 - cos(pc_i, aug_i)).
// N=16384 rows, D=1024 fp32 (128 MiB streamed).
// Main loop (proven 22.1us shape): 4 rows per 256-thread CTA (64 thr/row,
// 4 float4/tensor/thread -> MLP_p1=8), grid 4096, __ldcs streaming loads.
//
// Epilogue: HIERARCHICAL packed fixed-point atomics, fence-free, deterministic.
//   Level 1: 64 shard words (one 128B line each). CTA b does ONE u64 atomicAdd of
//            (1<<50 | fp_partial) to shard (b & 63). Same-address total order means
//            the packed count proves completion of that shard's sums.
//   Level 2: the CTA whose return shows shard count==64 carries the EXACT shard
//            total (old+own, pure dataflow - no loads, no fences) into one root
//            atomicAdd. Root count==64 -> compute mean, write out, reset.
// Integer adds -> bit-deterministic. Quantization 2^-32 relative, << 1e-3.

#define CL_N   16384
#define CL_D   1024
#define CL_EPS 1e-12f
#define GRID1  4096
#define NSHARD 64
#define CTAS_PER_SHARD (GRID1 / NSHARD)   // 64
#define SHARD_STRIDE 16                    // u64s; 128B per shard line
#define CNT_SHIFT 50
#define SUM_MASK  ((1ULL << CNT_SHIFT) - 1ULL)
#define FP_SCALE  4294967296.0            // 2^32
#define BIAS      8.0                     // per-CTA partial in (-8,16) -> biased (0,24)

__device__ unsigned long long g_shard[NSHARD * SHARD_STRIDE];  // zero-init
__device__ unsigned long long g_root = 0ULL;

__global__ __launch_bounds__(256)
void cos_loss_fused(const float* __restrict__ pc, const float* __restrict__ aug,
                    float* __restrict__ out) {
    const int t    = threadIdx.x;
    const int wid  = t >> 5;        // 0..7; warps 2r,2r+1 own row r
    const int lane = t & 31;
    const int rsub = t >> 6;        // 0..3: row within CTA
    const int ct   = t & 63;        // thread index within row (64 thr/row)
    const size_t row = (size_t)blockIdx.x * 4 + rsub;

    const float4* __restrict__ p4 = reinterpret_cast<const float4*>(pc  + row * CL_D);
    const float4* __restrict__ a4 = reinterpret_cast<const float4*>(aug + row * CL_D);

    // 8 outstanding LDG.128 per thread, streaming hint.
    float4 p0 = __ldcs(&p4[ct      ]);
    float4 p1 = __ldcs(&p4[ct +  64]);
    float4 p2 = __ldcs(&p4[ct + 128]);
    float4 p3 = __ldcs(&p4[ct + 192]);
    float4 a0 = __ldcs(&a4[ct      ]);
    float4 a1 = __ldcs(&a4[ct +  64]);
    float4 a2 = __ldcs(&a4[ct + 128]);
    float4 a3 = __ldcs(&a4[ct + 192]);

    float dot = p0.x*a0.x + p0.y*a0.y + p0.z*a0.z + p0.w*a0.w
              + p1.x*a1.x + p1.y*a1.y + p1.z*a1.z + p1.w*a1.w
              + p2.x*a2.x + p2.y*a2.y + p2.z*a2.z + p2.w*a2.w
              + p3.x*a3.x + p3.y*a3.y + p3.z*a3.z + p3.w*a3.w;
    float npp = p0.x*p0.x + p0.y*p0.y + p0.z*p0.z + p0.w*p0.w
              + p1.x*p1.x + p1.y*p1.y + p1.z*p1.z + p1.w*p1.w
              + p2.x*p2.x + p2.y*p2.y + p2.z*p2.z + p2.w*p2.w
              + p3.x*p3.x + p3.y*p3.y + p3.z*p3.z + p3.w*p3.w;
    float naa = a0.x*a0.x + a0.y*a0.y + a0.z*a0.z + a0.w*a0.w
              + a1.x*a1.x + a1.y*a1.y + a1.z*a1.z + a1.w*a1.w
              + a2.x*a2.x + a2.y*a2.y + a2.z*a2.z + a2.w*a2.w
              + a3.x*a3.x + a3.y*a3.y + a3.z*a3.z + a3.w*a3.w;

    #pragma unroll
    for (int off = 16; off > 0; off >>= 1) {
        dot += __shfl_down_sync(0xFFFFFFFFu, dot, off);
        npp += __shfl_down_sync(0xFFFFFFFFu, npp, off);
        naa += __shfl_down_sync(0xFFFFFFFFu, naa, off);
    }

    __shared__ float s_dot[8], s_npp[8], s_naa[8];
    if (lane == 0) {
        s_dot[wid] = dot;
        s_npp[wid] = npp;
        s_naa[wid] = naa;
    }
    __syncthreads();

    // Warp 0, lanes 0..7: slot pairs (2r, 2r+1) belong to row r.
    if (wid == 0 && lane < 8) {
        dot = s_dot[lane];
        npp = s_npp[lane];
        naa = s_naa[lane];
        dot += __shfl_xor_sync(0x000000FFu, dot, 1);
        npp += __shfl_xor_sync(0x000000FFu, npp, 1);
        naa += __shfl_xor_sync(0x000000FFu, naa, 1);

        float loss = 0.0f;
        if ((lane & 1) == 0) {
            float np_ = fmaxf(sqrtf(npp), CL_EPS);
            float na_ = fmaxf(sqrtf(naa), CL_EPS);
            loss = 1.0f - dot / (np_ * na_);
        }
        loss += __shfl_down_sync(0x000000FFu, loss, 4);
        loss += __shfl_down_sync(0x000000FFu, loss, 2);

        if (lane == 0) {
            // Fixed-point encode (non-negative after bias). fp < 24*2^32 < 2^37.
            unsigned long long fp =
                (unsigned long long)((double)loss * FP_SCALE + BIAS * FP_SCALE + 0.5);
            unsigned long long word = (1ULL << CNT_SHIFT) | fp;

            const int shard = (blockIdx.x & (NSHARD - 1)) * SHARD_STRIDE;
            unsigned long long old = atomicAdd(&g_shard[shard], word);
            unsigned long long mine = old + word;

            if ((mine >> CNT_SHIFT) == CTAS_PER_SHARD) {
                // This shard is complete; we hold its exact total as data.
                unsigned long long shard_sum = mine & SUM_MASK;   // < 64*24*2^32 < 2^43
                // Reset shard for next graph replay (no more adds to it this launch).
                atomicExch(&g_shard[shard], 0ULL);

                unsigned long long rword = (1ULL << CNT_SHIFT) | shard_sum;
                unsigned long long rold  = atomicAdd(&g_root, rword);
                unsigned long long rmine = rold + rword;

                if ((rmine >> CNT_SHIFT) == NSHARD) {
                    // Grand total: sum of all 4096 biased partials (< 2^49).
                    unsigned long long total = rmine & SUM_MASK;
                    double sum = (double)total * (1.0 / FP_SCALE) - BIAS * (double)GRID1;
                    out[0] = (float)(sum * (1.0 / (double)CL_N));
                    atomicExch(&g_root, 0ULL);   // reset for next graph replay
                }
            }
        }
    }
}

extern "C" void kernel_launch(void* const* d_in, const int* in_sizes, int n_in,
                              void* d_out, int out_size) {
    const float* pc  = (const float*)d_in[0];
    const float* aug = (const float*)d_in[1];
    float* out = (float*)d_out;

    cos_loss_fused<<<GRID1, 256>>>(pc, aug, out);
}

// round 11
// speedup vs baseline: 1.1515x; 1.0429x over previous
#include <cuda_runtime.h>

// CosinLoss fully fused, single kernel: loss = mean_i(1 - cos(pc_i, aug_i)).
// N=16384 rows, D=1024 fp32 (128 MiB streamed).
// Main loop (proven 22.1us shape): 4 rows per 256-thread CTA (64 thr/row,
// 4 float4/tensor/thread -> MLP_p1=8), grid 4096, __ldcs streaming loads.
//
// Epilogue: RETURN-FREE reduction. Each worker CTA issues ONE red.relaxed.gpu
// u64 add of a packed word (count<<50 | fixed_point_partial) and exits without
// waiting for any L2 round-trip. An extra poller CTA (blockIdx.x == GRID1) spins
// on an acquire-load of the word until count == GRID1; the low 50 bits then hold
// the exact integer grand total (same-address modification order). It writes the
// mean and resets the word for graph replay. No fences, no stalls on workers.
// Integer adds -> bit-deterministic; 2^-32 quantization << 1e-3 tolerance.

#define CL_N   16384
#define CL_D   1024
#define CL_EPS 1e-12f
#define GRID1  4096
#define CNT_SHIFT 50
#define SUM_MASK  ((1ULL << CNT_SHIFT) - 1ULL)
#define FP_SCALE  4294967296.0    // 2^32
#define BIAS      8.0             // per-CTA partial in (-8,16) -> biased (0,24); 4096*24*2^32 < 2^49

__device__ unsigned long long g_accum = 0ULL;

__global__ __launch_bounds__(256)
void cos_loss_fused(const float* __restrict__ pc, const float* __restrict__ aug,
                    float* __restrict__ out) {
    // ---------------- Poller CTA ----------------
    if (blockIdx.x == GRID1) {
        if (threadIdx.x == 0) {
            unsigned long long v;
            while (true) {
                asm volatile("ld.acquire.gpu.global.b64 %0, [%1];"
                             : "=l"(v) : "l"(&g_accum) : "memory");
                if ((v >> CNT_SHIFT) == GRID1) break;
                __nanosleep(128);
            }
            unsigned long long total = v & SUM_MASK;
            double sum = (double)total * (1.0 / FP_SCALE) - BIAS * (double)GRID1;
            out[0] = (float)(sum * (1.0 / (double)CL_N));
            // Reset for next graph replay (all adds for this launch are in v).
            asm volatile("st.global.cg.b64 [%0], %1;" :: "l"(&g_accum), "l"(0ULL) : "memory");
        }
        return;
    }

    // ---------------- Worker CTAs ----------------
    const int t    = threadIdx.x;
    const int wid  = t >> 5;        // 0..7; warps 2r,2r+1 own row r
    const int lane = t & 31;
    const int rsub = t >> 6;        // 0..3: row within CTA
    const int ct   = t & 63;        // thread index within row (64 thr/row)
    const size_t row = (size_t)blockIdx.x * 4 + rsub;

    const float4* __restrict__ p4 = reinterpret_cast<const float4*>(pc  + row * CL_D);
    const float4* __restrict__ a4 = reinterpret_cast<const float4*>(aug + row * CL_D);

    // 8 outstanding LDG.128 per thread, streaming hint.
    float4 p0 = __ldcs(&p4[ct      ]);
    float4 p1 = __ldcs(&p4[ct +  64]);
    float4 p2 = __ldcs(&p4[ct + 128]);
    float4 p3 = __ldcs(&p4[ct + 192]);
    float4 a0 = __ldcs(&a4[ct      ]);
    float4 a1 = __ldcs(&a4[ct +  64]);
    float4 a2 = __ldcs(&a4[ct + 128]);
    float4 a3 = __ldcs(&a4[ct + 192]);

    float dot = p0.x*a0.x + p0.y*a0.y + p0.z*a0.z + p0.w*a0.w
              + p1.x*a1.x + p1.y*a1.y + p1.z*a1.z + p1.w*a1.w
              + p2.x*a2.x + p2.y*a2.y + p2.z*a2.z + p2.w*a2.w
              + p3.x*a3.x + p3.y*a3.y + p3.z*a3.z + p3.w*a3.w;
    float npp = p0.x*p0.x + p0.y*p0.y + p0.z*p0.z + p0.w*p0.w
              + p1.x*p1.x + p1.y*p1.y + p1.z*p1.z + p1.w*p1.w
              + p2.x*p2.x + p2.y*p2.y + p2.z*p2.z + p2.w*p2.w
              + p3.x*p3.x + p3.y*p3.y + p3.z*p3.z + p3.w*p3.w;
    float naa = a0.x*a0.x + a0.y*a0.y + a0.z*a0.z + a0.w*a0.w
              + a1.x*a1.x + a1.y*a1.y + a1.z*a1.z + a1.w*a1.w
              + a2.x*a2.x + a2.y*a2.y + a2.z*a2.z + a2.w*a2.w
              + a3.x*a3.x + a3.y*a3.y + a3.z*a3.z + a3.w*a3.w;

    #pragma unroll
    for (int off = 16; off > 0; off >>= 1) {
        dot += __shfl_down_sync(0xFFFFFFFFu, dot, off);
        npp += __shfl_down_sync(0xFFFFFFFFu, npp, off);
        naa += __shfl_down_sync(0xFFFFFFFFu, naa, off);
    }

    __shared__ float s_dot[8], s_npp[8], s_naa[8];
    if (lane == 0) {
        s_dot[wid] = dot;
        s_npp[wid] = npp;
        s_naa[wid] = naa;
    }
    __syncthreads();

    // Warp 0, lanes 0..7: slot pairs (2r, 2r+1) belong to row r.
    if (wid == 0 && lane < 8) {
        dot = s_dot[lane];
        npp = s_npp[lane];
        naa = s_naa[lane];
        dot += __shfl_xor_sync(0x000000FFu, dot, 1);
        npp += __shfl_xor_sync(0x000000FFu, npp, 1);
        naa += __shfl_xor_sync(0x000000FFu, naa, 1);

        float loss = 0.0f;
        if ((lane & 1) == 0) {
            float np_ = fmaxf(sqrtf(npp), CL_EPS);
            float na_ = fmaxf(sqrtf(naa), CL_EPS);
            loss = 1.0f - dot / (np_ * na_);
        }
        loss += __shfl_down_sync(0x000000FFu, loss, 4);
        loss += __shfl_down_sync(0x000000FFu, loss, 2);

        if (lane == 0) {
            // Fixed-point encode (non-negative after bias). fp < 24*2^32 < 2^37.
            unsigned long long fp =
                (unsigned long long)((double)loss * FP_SCALE + BIAS * FP_SCALE + 0.5);
            unsigned long long word = (1ULL << CNT_SHIFT) | fp;
            // No-return reduction: no L2 round-trip on the worker's critical path.
            asm volatile("red.relaxed.gpu.global.add.u64 [%0], %1;"
                         :: "l"(&g_accum), "l"(word) : "memory");
        }
    }
}

extern "C" void kernel_launch(void* const* d_in, const int* in_sizes, int n_in,
                              void* d_out, int out_size) {
    const float* pc  = (const float*)d_in[0];
    const float* aug = (const float*)d_in[1];
    float* out = (float*)d_out;

    cos_loss_fused<<<GRID1 + 1, 256>>>(pc, aug, out);
}